// round 17
// baseline (speedup 1.0000x reference)
#include <cuda_runtime.h>
#include <cuda_fp16.h>
#include <math.h>

#define B_   2
#define N_   4096
#define IC_  256
#define PC_  128
#define OC_  128
#define SCALE_ 0.08838834764831845f   // 1/sqrt(128)
#define VSCALE 4096.0f                 // vT scaling to stay in fp16 normal range
#define LDH  40                        // fp16 tile pitch (halves), 80 B/row
#define BUFH (128u * LDH * 2u)         // 10240 B per fp16 plane
#define KSPL (N_ / 2)                  // 2-way k-split for k_av
#define LDT  136                       // staging / K-major tile pitch (halves)
#define TKB  (32u * LDT * 2u)          // 8704 B per K-major A plane (32 k-rows)
#define KAV_SMEM (6u * BUFH)           // 61440 B: 3-stage A + B planes

// ---------------- scratch (device globals) ----------------------------------
static __device__ __align__(16) __half g_rp16[(size_t)B_ * N_ * PC_];
static __device__ __align__(16) __half g_ri16[(size_t)B_ * N_ * PC_];
static __device__ __align__(16) __half g_S16 [(size_t)B_ * N_ * N_];   // P
static __device__ __align__(16) __half g_vT16[2][(size_t)B_ * OC_ * N_]; // v^T * VSCALE
static __device__ __align__(16) float  g_csum[B_ * N_];
static __device__ __align__(16) float  g_rsum[B_ * N_];
static __device__ __align__(16) float  g_d   [4][(size_t)B_ * N_ * OC_]; // fp32 partials

// ---------------- helpers ----------------------------------------------------
__device__ __forceinline__ unsigned h2pack(float a, float b) {
    __half2 h = __floats2half2_rn(a, b);
    return *reinterpret_cast<unsigned*>(&h);
}
__device__ __forceinline__ void mma_f16(float* c, unsigned a0, unsigned a1,
                                        unsigned a2, unsigned a3,
                                        unsigned b0, unsigned b1) {
    asm volatile(
        "mma.sync.aligned.m16n8k16.row.col.f32.f16.f16.f32 "
        "{%0,%1,%2,%3}, {%4,%5,%6,%7}, {%8,%9}, {%0,%1,%2,%3};"
        : "+f"(c[0]), "+f"(c[1]), "+f"(c[2]), "+f"(c[3])
        : "r"(a0), "r"(a1), "r"(a2), "r"(a3), "r"(b0), "r"(b1));
}
__device__ __forceinline__ unsigned smem_u32(const void* p) {
    unsigned a;
    asm("{.reg .u64 t; cvta.to.shared.u64 t, %1; cvt.u32.u64 %0, t;}"
        : "=r"(a) : "l"(p));
    return a;
}
__device__ __forceinline__ void ldsm4(unsigned& r0, unsigned& r1,
                                      unsigned& r2, unsigned& r3, unsigned addr) {
    asm volatile("ldmatrix.sync.aligned.m8n8.x4.shared.b16 {%0,%1,%2,%3}, [%4];"
                 : "=r"(r0), "=r"(r1), "=r"(r2), "=r"(r3) : "r"(addr));
}
__device__ __forceinline__ void ldsm4t(unsigned& r0, unsigned& r1,
                                       unsigned& r2, unsigned& r3, unsigned addr) {
    asm volatile("ldmatrix.sync.aligned.m8n8.x4.trans.shared.b16 {%0,%1,%2,%3}, [%4];"
                 : "=r"(r0), "=r"(r1), "=r"(r2), "=r"(r3) : "r"(addr));
}
#define CPA16(dst, src) asm volatile("cp.async.cg.shared.global [%0], [%1], 16;" \
                                     :: "r"(dst), "l"(src) : "memory")
#define CPA_COMMIT()    asm volatile("cp.async.commit_group;" ::: "memory")
#define CPA_WAIT0()     asm volatile("cp.async.wait_group 0;" ::: "memory")
#define CPA_WAIT1()     asm volatile("cp.async.wait_group 1;" ::: "memory")
#define CPA_WAIT2()     asm volatile("cp.async.wait_group 2;" ::: "memory")

#define WARP_COORDS                                                          \
    const int tid  = threadIdx.x;                                            \
    const int lane = tid & 31, wid = tid >> 5;                               \
    const int wm = wid & 1, wn = wid >> 1;                                   \
    const int g = lane >> 2, t = lane & 3;                                   \
    const int jm = lane >> 3;                                                \
    (void)g; (void)t; (void)jm;

#define ZERO_ACC                                                             \
    float acc[4][4][4];                                                      \
    _Pragma("unroll")                                                        \
    for (int mf = 0; mf < 4; mf++)                                           \
        _Pragma("unroll")                                                    \
        for (int nf = 0; nf < 4; nf++)                                       \
            _Pragma("unroll")                                                 \
            for (int q = 0; q < 4; q++) acc[mf][nf][q] = 0.f;

#define ZERO_ACC2                                                            \
    float acc[2][4][4];                                                      \
    _Pragma("unroll")                                                        \
    for (int mf = 0; mf < 2; mf++)                                           \
        _Pragma("unroll")                                                    \
        for (int nf = 0; nf < 4; nf++)                                       \
            _Pragma("unroll")                                                 \
            for (int q = 0; q < 4; q++) acc[mf][nf][q] = 0.f;

// ----- fp16 path: BK = 32 halves -----
#define LDSM16_BASES_U(aU, bU)                                               \
    const unsigned baseA = (aU) +                                            \
        ((((wm * 64) + (lane & 15)) * LDH + ((lane >> 4) * 8)) * 2u);        \
    const unsigned baseB = (bU) +                                            \
        ((((wn * 32) + (lane & 7) + ((lane >> 4) * 8)) * LDH +               \
          (((lane >> 3) & 1) * 8)) * 2u);

#define LDSMT_BASE(aU)                                                       \
    const unsigned baseAT = (aU) +                                           \
        ((((lane & 7) + ((jm >> 1) * 8)) * LDT) + (wm * 64) + ((jm & 1) * 8)) * 2u;

#define MMA16_TILE_BODY(offA, offB)                                          \
    _Pragma("unroll")                                                        \
    for (int kk = 0; kk < 2; kk++) {                                         \
        unsigned a[4][4], bb[4][2];                                          \
        _Pragma("unroll")                                                    \
        for (int mf = 0; mf < 4; mf++)                                       \
            ldsm4(a[mf][0], a[mf][1], a[mf][2], a[mf][3],                    \
                  baseA + (offA) + (mf * 16 * LDH + kk * 16) * 2u);          \
        ldsm4(bb[0][0], bb[0][1], bb[1][0], bb[1][1],                        \
              baseB + (offB) + (kk * 16) * 2u);                              \
        ldsm4(bb[2][0], bb[2][1], bb[3][0], bb[3][1],                        \
              baseB + (offB) + (16 * LDH + kk * 16) * 2u);                   \
        _Pragma("unroll")                                                    \
        for (int mf = 0; mf < 4; mf++)                                       \
            _Pragma("unroll")                                                \
            for (int nf = 0; nf < 4; nf++)                                   \
                mma_f16(acc[mf][nf], a[mf][0], a[mf][1], a[mf][2], a[mf][3], \
                        bb[nf][0], bb[nf][1]);                               \
    }

// M=64 variant: 2 m-frags, A base supplied with wm*32 offset.
#define MMA16_TILE_BODY_M64(offA, offB)                                      \
    _Pragma("unroll")                                                        \
    for (int kk = 0; kk < 2; kk++) {                                         \
        unsigned a[2][4], bb[4][2];                                          \
        _Pragma("unroll")                                                    \
        for (int mf = 0; mf < 2; mf++)                                       \
            ldsm4(a[mf][0], a[mf][1], a[mf][2], a[mf][3],                    \
                  baseA64 + (offA) + (mf * 16 * LDH + kk * 16) * 2u);        \
        ldsm4(bb[0][0], bb[0][1], bb[1][0], bb[1][1],                        \
              baseB + (offB) + (kk * 16) * 2u);                              \
        ldsm4(bb[2][0], bb[2][1], bb[3][0], bb[3][1],                        \
              baseB + (offB) + (16 * LDH + kk * 16) * 2u);                   \
        _Pragma("unroll")                                                    \
        for (int mf = 0; mf < 2; mf++)                                       \
            _Pragma("unroll")                                                \
            for (int nf = 0; nf < 4; nf++)                                   \
                mma_f16(acc[mf][nf], a[mf][0], a[mf][1], a[mf][2], a[mf][3], \
                        bb[nf][0], bb[nf][1]);                               \
    }

// transposed-A variant: A tile is K-major [32 k-rows][128 m-cols], pitch LDT.
#define MMA16_TILE_BODY_T(offA, offB)                                        \
    _Pragma("unroll")                                                        \
    for (int kk = 0; kk < 2; kk++) {                                         \
        unsigned a[4][4], bb[4][2];                                          \
        _Pragma("unroll")                                                    \
        for (int mf = 0; mf < 4; mf++)                                       \
            ldsm4t(a[mf][0], a[mf][1], a[mf][2], a[mf][3],                   \
                   baseAT + (offA) + (kk * 16 * LDT + mf * 16) * 2u);        \
        ldsm4(bb[0][0], bb[0][1], bb[1][0], bb[1][1],                        \
              baseB + (offB) + (kk * 16) * 2u);                              \
        ldsm4(bb[2][0], bb[2][1], bb[3][0], bb[3][1],                        \
              baseB + (offB) + (16 * LDH + kk * 16) * 2u);                   \
        _Pragma("unroll")                                                    \
        for (int mf = 0; mf < 4; mf++)                                       \
            _Pragma("unroll")                                                \
            for (int nf = 0; nf < 4; nf++)                                   \
                mma_f16(acc[mf][nf], a[mf][0], a[mf][1], a[mf][2], a[mf][3], \
                        bb[nf][0], bb[nf][1]);                               \
    }

// ---------------- kernel 1: transpose pf -> rp16, plus zero sums -------------
__global__ void k_transpose(const float* __restrict__ pf) {
    __shared__ float tile[32][33];
    const int b  = blockIdx.z;
    const int n0 = blockIdx.x * 32;
    const int d0 = blockIdx.y * 32;
    const float* src = pf + (size_t)b * PC_ * N_;
    __half*      dst = g_rp16 + (size_t)b * N_ * PC_;
    const int tx = threadIdx.x, ty = threadIdx.y;   // (32, 8)
    if (blockIdx.y == 0) {                           // fold in k_zero
        int lt = ty * 32 + tx;
        if (lt < 32) {
            int zi = (b * (N_ / 32) + blockIdx.x) * 32 + lt;
            g_csum[zi] = 0.f; g_rsum[zi] = 0.f;
        }
    }
#pragma unroll
    for (int j = 0; j < 32; j += 8)
        tile[ty + j][tx] = src[(size_t)(d0 + ty + j) * N_ + n0 + tx];
    __syncthreads();
#pragma unroll
    for (int j = 0; j < 32; j += 8)
        dst[(size_t)(n0 + ty + j) * PC_ + d0 + tx] = __float2half_rn(tile[tx][ty + j]);
}

// ---------------- kernel 2: ri16 = half(img^T @ fc2_w^T + fc2_b)  (fp16 mma) -
__global__ __launch_bounds__(256, 2) void k_ri(const float* __restrict__ img,
                                               const float* __restrict__ w,
                                               const float* __restrict__ bias) {
    const int b  = blockIdx.y;
    const int n0 = blockIdx.x * 128;
    const float* X = img + (size_t)b * IC_ * N_;
    __half*      R = g_ri16 + (size_t)b * N_ * PC_;

    __shared__ __align__(16) char blob[2 * TKB + 2 * BUFH];

    WARP_COORDS
    const unsigned sAu = smem_u32(blob);
    const unsigned sBu = sAu + 2 * TKB;
    LDSMT_BASE(sAu)
    const unsigned baseB = sBu +
        ((((wn * 32) + (lane & 7) + ((lane >> 4) * 8)) * LDH +
          (((lane >> 3) & 1) * 8)) * 2u);

    const int trow = tid >> 3, tn0 = (tid & 7) * 16;  // A: c-row, 16-n segment
    const int frow = tid >> 1, fg0 = (tid & 1) * 2;   // B: d-row, c-quads

    ZERO_ACC

    float4 xa[4]; float4 wb[2];
#pragma unroll
    for (int r = 0; r < 4; r++)
        xa[r] = *(const float4*)&X[(size_t)trow * N_ + n0 + tn0 + r * 4];
#pragma unroll
    for (int r = 0; r < 2; r++)
        wb[r] = *(const float4*)&w[(size_t)frow * IC_ + (fg0 + r) * 8];

    int p = 0;
    for (int ch = 0; ch < IC_ / 32; ch++) {
        {
            uint4 u0 = make_uint4(h2pack(xa[0].x, xa[0].y), h2pack(xa[0].z, xa[0].w),
                                  h2pack(xa[1].x, xa[1].y), h2pack(xa[1].z, xa[1].w));
            uint4 u1 = make_uint4(h2pack(xa[2].x, xa[2].y), h2pack(xa[2].z, xa[2].w),
                                  h2pack(xa[3].x, xa[3].y), h2pack(xa[3].z, xa[3].w));
            char* ap = blob + p * TKB + (trow * LDT + tn0) * 2;
            *(uint4*)ap = u0; *(uint4*)(ap + 16) = u1;
#pragma unroll
            for (int r = 0; r < 2; r++) {
                int gq = fg0 + r;
                float4 v0 = wb[r];
                float4 v1 = *(const float4*)&w[(size_t)frow * IC_ + ch * 32 + gq * 8 + 4];
                *(uint4*)(blob + 2 * TKB + p * BUFH + (frow * LDH + gq * 8) * 2) =
                    make_uint4(h2pack(v0.x, v0.y), h2pack(v0.z, v0.w),
                               h2pack(v1.x, v1.y), h2pack(v1.z, v1.w));
            }
        }
        __syncthreads();
        if (ch + 1 < IC_ / 32) {
            int kn = (ch + 1) * 32;
#pragma unroll
            for (int r = 0; r < 4; r++)
                xa[r] = *(const float4*)&X[(size_t)(kn + trow) * N_ + n0 + tn0 + r * 4];
#pragma unroll
            for (int r = 0; r < 2; r++)
                wb[r] = *(const float4*)&w[(size_t)frow * IC_ + kn + (fg0 + r) * 8];
        }
        MMA16_TILE_BODY_T(p * TKB, p * BUFH)
        __syncthreads();
        p ^= 1;
    }

#pragma unroll
    for (int mf = 0; mf < 4; mf++) {
        int row = n0 + wm * 64 + mf * 16 + g;
#pragma unroll
        for (int nf = 0; nf < 4; nf++) {
            int col = wn * 32 + nf * 8 + 2 * t;
            float b0 = bias[col], b1 = bias[col + 1];
            *(unsigned*)&R[(size_t)row * PC_ + col] =
                h2pack(acc[mf][nf][0] + b0, acc[mf][nf][1] + b1);
            *(unsigned*)&R[(size_t)(row + 8) * PC_ + col] =
                h2pack(acc[mf][nf][2] + b0, acc[mf][nf][3] + b1);
        }
    }
}

// ---------------- kernel 3: P = exp(scale * rp @ ri^T); staged P, sums -------
__global__ __launch_bounds__(256, 2) void k_s() {
    const int b  = blockIdx.z;
    const int i0 = blockIdx.y * 128;
    const int j0 = blockIdx.x * 128;
    const __half* A16 = g_rp16 + (size_t)b * N_ * PC_ + (size_t)i0 * PC_;
    const __half* B16 = g_ri16 + (size_t)b * N_ * PC_ + (size_t)j0 * PC_;
    __half*       Pp  = g_S16  + (size_t)b * N_ * N_;

    __shared__ __align__(16) char blob[4 * BUFH];
    __shared__ float shr[128], shc[128];

    WARP_COORDS

    const unsigned sAu = smem_u32(blob);
    const unsigned sBu = sAu + 2 * BUFH;
    LDSM16_BASES_U(sAu, sBu)

    const int frow = tid >> 1, fg0 = (tid & 1) * 2;

#define FILL_S16(pp, kk0)                                                    \
    _Pragma("unroll")                                                        \
    for (int r = 0; r < 2; r++) {                                            \
        int gq = fg0 + r;                                                    \
        unsigned o = (pp) * BUFH + ((unsigned)frow * LDH + gq * 8) * 2u;     \
        CPA16(sAu + o, A16 + (size_t)frow * PC_ + (kk0) + gq * 8);           \
        CPA16(sBu + o, B16 + (size_t)frow * PC_ + (kk0) + gq * 8);           \
    }                                                                        \
    CPA_COMMIT();

    ZERO_ACC

    FILL_S16(0, 0)
    int p = 0;
    for (int ch = 0; ch < 4; ch++) {
        if (ch + 1 < 4) { FILL_S16(p ^ 1, (ch + 1) * 32) CPA_WAIT1(); }
        else            { CPA_WAIT0(); }
        __syncthreads();
        MMA16_TILE_BODY(p * BUFH, p * BUFH)
        __syncthreads();
        p ^= 1;
    }
#undef FILL_S16

    __half* Psm = (__half*)blob;
    if (tid < 128) { shr[tid] = 0.f; shc[tid] = 0.f; }
    __syncthreads();

    float rs[4][2] = {{0.f,0.f},{0.f,0.f},{0.f,0.f},{0.f,0.f}};
    float cs[4][2] = {{0.f,0.f},{0.f,0.f},{0.f,0.f},{0.f,0.f}};
#pragma unroll
    for (int mf = 0; mf < 4; mf++) {
        int rl = wm * 64 + mf * 16 + g;
#pragma unroll
        for (int nf = 0; nf < 4; nf++) {
            int cl = wn * 32 + nf * 8 + 2 * t;
            float p0 = __expf(acc[mf][nf][0] * SCALE_);
            float p1 = __expf(acc[mf][nf][1] * SCALE_);
            float p2 = __expf(acc[mf][nf][2] * SCALE_);
            float p3 = __expf(acc[mf][nf][3] * SCALE_);
            *(unsigned*)&Psm[rl * LDT + cl]       = h2pack(p0, p1);
            *(unsigned*)&Psm[(rl + 8) * LDT + cl] = h2pack(p2, p3);
            rs[mf][0] += p0 + p1; rs[mf][1] += p2 + p3;
            cs[nf][0] += p0 + p2; cs[nf][1] += p1 + p3;
        }
    }
#pragma unroll
    for (int mf = 0; mf < 4; mf++)
#pragma unroll
        for (int h = 0; h < 2; h++) {
            float v = rs[mf][h];
            v += __shfl_xor_sync(0xffffffffu, v, 1);
            v += __shfl_xor_sync(0xffffffffu, v, 2);
            if (t == 0) atomicAdd(&shr[wm * 64 + mf * 16 + h * 8 + g], v);
        }
#pragma unroll
    for (int nf = 0; nf < 4; nf++)
#pragma unroll
        for (int q = 0; q < 2; q++) {
            float v = cs[nf][q];
            v += __shfl_xor_sync(0xffffffffu, v, 4);
            v += __shfl_xor_sync(0xffffffffu, v, 8);
            v += __shfl_xor_sync(0xffffffffu, v, 16);
            if (g == 0) atomicAdd(&shc[wn * 32 + nf * 8 + 2 * t + q], v);
        }
    __syncthreads();

#pragma unroll
    for (int i = tid; i < 128 * 16; i += 256) {
        int r = i >> 4, chk = i & 15;
        uint4 v = *(uint4*)&Psm[r * LDT + chk * 8];
        *(uint4*)&Pp[(size_t)(i0 + r) * N_ + j0 + chk * 8] = v;
    }
    if (tid < 128) {
        atomicAdd(&g_rsum[b * N_ + i0 + tid], shr[tid]);
        atomicAdd(&g_csum[b * N_ + j0 + tid], shc[tid]);
    }
}

// ---------------- kernel 4: vT16, M=64 tiles (grid 64 x 2 x B) ---------------
__global__ __launch_bounds__(256, 2) void k_vp(const float* __restrict__ w) {
    const int which = blockIdx.y;
    const int b  = blockIdx.z;
    const int j0 = blockIdx.x * 64;
    const __half* Src = (which ? g_ri16 : g_rp16) + (size_t)b * N_ * PC_ + (size_t)j0 * PC_;
    const float*  sum = (which ? g_rsum : g_csum) + b * N_;
    __half*       Dst = g_vT16[which] + (size_t)b * OC_ * N_;

    __shared__ __align__(16) char blob[4 * BUFH];

    WARP_COORDS

    const unsigned sAu = smem_u32(blob);
    const unsigned sBu = sAu + 2 * BUFH;
    const unsigned baseA64 = sAu +
        ((((wm * 32) + (lane & 15)) * LDH + ((lane >> 4) * 8)) * 2u);
    const unsigned baseB = sBu +
        ((((wn * 32) + (lane & 7) + ((lane >> 4) * 8)) * LDH +
          (((lane >> 3) & 1) * 8)) * 2u);

    const int arow = tid >> 2, asg = tid & 3;         // A: 64 rows x 4 segs
    const int frow = tid >> 1, fg0 = (tid & 1) * 2;   // B: 128 rows x 2 quads

    ZERO_ACC2

#define FILL_VP(pp, kk0)                                                     \
    CPA16(sAu + (pp) * BUFH + ((unsigned)arow * LDH + asg * 8) * 2u,         \
          Src + (size_t)arow * PC_ + (kk0) + asg * 8);                       \
    _Pragma("unroll")                                                        \
    for (int r = 0; r < 2; r++) {                                            \
        int gq = fg0 + r;                                                    \
        const float* ws = &w[(size_t)frow * (2 * PC_) + which * PC_ + (kk0) + gq * 8]; \
        float4 v0 = *(const float4*)ws, v1 = *(const float4*)(ws + 4);       \
        *(uint4*)(blob + 2 * BUFH + (pp) * BUFH + (frow * LDH + gq * 8) * 2) = \
            make_uint4(h2pack(v0.x, v0.y), h2pack(v0.z, v0.w),               \
                       h2pack(v1.x, v1.y), h2pack(v1.z, v1.w));              \
    }                                                                        \
    CPA_COMMIT();

    FILL_VP(0, 0)
    int p = 0;
    for (int ch = 0; ch < 4; ch++) {
        if (ch + 1 < 4) { FILL_VP(p ^ 1, (ch + 1) * 32) CPA_WAIT1(); }
        else            { CPA_WAIT0(); }
        __syncthreads();
        MMA16_TILE_BODY_M64(p * BUFH, p * BUFH)
        __syncthreads();
        p ^= 1;
    }
#undef FILL_VP

    __half* Vsm = (__half*)blob;    // staged [128 c][64 rl] pitch LDT
#pragma unroll
    for (int mf = 0; mf < 2; mf++) {
        int rl = wm * 32 + mf * 16 + g;
        float inv0 = __fdividef(VSCALE, sum[j0 + rl]);
        float inv8 = __fdividef(VSCALE, sum[j0 + rl + 8]);
#pragma unroll
        for (int nf = 0; nf < 4; nf++) {
            int cl = wn * 32 + nf * 8 + 2 * t;
            Vsm[cl * LDT + rl]           = __float2half_rn(acc[mf][nf][0] * inv0);
            Vsm[(cl + 1) * LDT + rl]     = __float2half_rn(acc[mf][nf][1] * inv0);
            Vsm[cl * LDT + rl + 8]       = __float2half_rn(acc[mf][nf][2] * inv8);
            Vsm[(cl + 1) * LDT + rl + 8] = __float2half_rn(acc[mf][nf][3] * inv8);
        }
    }
    __syncthreads();
#pragma unroll
    for (int i = tid; i < 128 * 8; i += 256) {
        int c = i >> 3, chk = i & 7;
        uint4 v = *(uint4*)&Vsm[c * LDT + chk * 8];
        *(uint4*)&Dst[(size_t)c * N_ + j0 + chk * 8] = v;
    }
}

// ---------------- kernel 5: AV partial GEMMs (3-stage pipeline, 2 k-splits) --
__global__ __launch_bounds__(256, 2) void k_av() {
    extern __shared__ __align__(16) char dyn[];    // KAV_SMEM bytes
    const int mode = blockIdx.x & 1;
    const int ks   = blockIdx.x >> 1;              // 0..1
    const int b    = blockIdx.z;
    const int i0   = blockIdx.y * 128;
    const int kb   = ks * KSPL;
    const __half* Pb = g_S16 + (size_t)b * N_ * N_;
    const __half* M0 = Pb + (size_t)i0 * N_;
    const __half* Vt = g_vT16[mode] + (size_t)b * OC_ * N_;
    float*        D  = g_d[(mode << 1) | ks] + (size_t)b * N_ * OC_;

    WARP_COORDS

    const unsigned sAu = smem_u32(dyn);
    const unsigned sBu = sAu + 3 * BUFH;
    LDSM16_BASES_U(sAu, sBu)
    LDSMT_BASE(sAu)

    const int frow = tid >> 1, fg0 = (tid & 1) * 2;
    const int trow = tid >> 3, tseg = tid & 7;

#define FILL_A0(ss, kk0)                                                     \
    _Pragma("unroll")                                                        \
    for (int r = 0; r < 2; r++) {                                            \
        int gq = fg0 + r;                                                    \
        CPA16(sAu + (ss) * BUFH + ((unsigned)frow * LDH + gq * 8) * 2u,      \
              M0 + (size_t)frow * N_ + (kk0) + gq * 8);                      \
    }
#define FILL_A1(ss, kk0)                                                     \
    _Pragma("unroll")                                                        \
    for (int r = 0; r < 2; r++) {                                            \
        int seg = tseg + r * 8;                                              \
        CPA16(sAu + (ss) * BUFH + ((unsigned)trow * LDT + seg * 8) * 2u,     \
              Pb + (size_t)((kk0) + trow) * N_ + i0 + seg * 8);              \
    }
#define FILL_B(ss, kk0)                                                      \
    _Pragma("unroll")                                                        \
    for (int r = 0; r < 2; r++) {                                            \
        int gq = fg0 + r;                                                    \
        CPA16(sBu + (ss) * BUFH + ((unsigned)frow * LDH + gq * 8) * 2u,      \
              Vt + (size_t)frow * N_ + (kk0) + gq * 8);                      \
    }

    ZERO_ACC

    const int NCH = KSPL / 32;
    if (mode == 0) {
        FILL_A0(0, kb) FILL_B(0, kb) CPA_COMMIT();
        FILL_A0(1, kb + 32) FILL_B(1, kb + 32) CPA_COMMIT();
        for (int ch = 0; ch < NCH; ch++) {
            int s = ch % 3;
            if (ch + 2 < NCH) {
                int sn = (ch + 2) % 3, kn = kb + (ch + 2) * 32;
                FILL_A0(sn, kn) FILL_B(sn, kn) CPA_COMMIT(); CPA_WAIT2();
            } else if (ch + 1 < NCH) CPA_WAIT1(); else CPA_WAIT0();
            __syncthreads();
            MMA16_TILE_BODY(s * BUFH, s * BUFH)
            __syncthreads();
        }
    } else {
        FILL_A1(0, kb) FILL_B(0, kb) CPA_COMMIT();
        FILL_A1(1, kb + 32) FILL_B(1, kb + 32) CPA_COMMIT();
        for (int ch = 0; ch < NCH; ch++) {
            int s = ch % 3;
            if (ch + 2 < NCH) {
                int sn = (ch + 2) % 3, kn = kb + (ch + 2) * 32;
                FILL_A1(sn, kn) FILL_B(sn, kn) CPA_COMMIT(); CPA_WAIT2();
            } else if (ch + 1 < NCH) CPA_WAIT1(); else CPA_WAIT0();
            __syncthreads();
            MMA16_TILE_BODY_T(s * BUFH, s * BUFH)
            __syncthreads();
        }
    }
#undef FILL_A0
#undef FILL_A1
#undef FILL_B

#pragma unroll
    for (int mf = 0; mf < 4; mf++) {
        int row = i0 + wm * 64 + mf * 16 + g;
#pragma unroll
        for (int nf = 0; nf < 4; nf++) {
            int col = wn * 32 + nf * 8 + 2 * t;
            *(float2*)&D[(size_t)row * OC_ + col]       = make_float2(acc[mf][nf][0], acc[mf][nf][1]);
            *(float2*)&D[(size_t)(row + 8) * OC_ + col] = make_float2(acc[mf][nf][2], acc[mf][nf][3]);
        }
    }
}

// ---------------- kernel 6: sum 4 partials/VSCALE + BN + ReLU + transpose ----
__global__ void k_bn(const float* __restrict__ cb,    const float* __restrict__ gamma,
                     const float* __restrict__ beta,  const float* __restrict__ mean,
                     const float* __restrict__ var,   float* __restrict__ out) {
    __shared__ float tile[32][33];
    const int b  = blockIdx.z;
    const int n0 = blockIdx.x * 32;
    const int o0 = blockIdx.y * 32;
    const int tx = threadIdx.x, ty = threadIdx.y;   // (32, 8)
#pragma unroll
    for (int j = 0; j < 32; j += 8) {
        size_t idx = (size_t)b * N_ * OC_ + (size_t)(n0 + ty + j) * OC_ + o0 + tx;
        float s = 0.f;
#pragma unroll
        for (int m = 0; m < 4; m++) s += g_d[m][idx];
        tile[ty + j][tx] = s * (1.0f / VSCALE);
    }
    __syncthreads();
#pragma unroll
    for (int j = 0; j < 32; j += 8) {
        int o = o0 + ty + j;
        float gm   = gamma[o] * rsqrtf(var[o] + 1e-5f);
        float base = gm * (cb[o] - mean[o]) + beta[o];
        out[(size_t)b * OC_ * N_ + (size_t)o * N_ + n0 + tx] =
            fmaxf(gm * tile[tx][ty + j] + base, 0.f);
    }
}

// ---------------- launch -----------------------------------------------------
extern "C" void kernel_launch(void* const* d_in, const int* in_sizes, int n_in,
                              void* d_out, int out_size) {
    const float* pf     = (const float*)d_in[0];
    const float* img    = (const float*)d_in[1];
    const float* fc2_w  = (const float*)d_in[2];
    const float* fc2_b  = (const float*)d_in[3];
    const float* conv_w = (const float*)d_in[4];
    const float* conv_b = (const float*)d_in[5];
    const float* gamma  = (const float*)d_in[6];
    const float* beta   = (const float*)d_in[7];
    const float* mean   = (const float*)d_in[8];
    const float* var    = (const float*)d_in[9];
    float* out = (float*)d_out;

    cudaFuncSetAttribute(k_av, cudaFuncAttributeMaxDynamicSharedMemorySize, KAV_SMEM);

    k_transpose<<<dim3(N_ / 32, PC_ / 32, B_), dim3(32, 8)>>>(pf);
    k_ri       <<<dim3(N_ / 128, B_),           256>>>(img, fc2_w, fc2_b);
    k_s        <<<dim3(N_ / 128, N_ / 128, B_), 256>>>();
    k_vp       <<<dim3(N_ / 64, 2, B_),         256>>>(conv_w);
    k_av       <<<dim3(4, N_ / 128, B_),        256, KAV_SMEM>>>();
    k_bn       <<<dim3(N_ / 32, OC_ / 32, B_),  dim3(32, 8)>>>(conv_b, gamma, beta,
                                                               mean, var, out);
}